// round 1
// baseline (speedup 1.0000x reference)
#include <cuda_runtime.h>

// out[s,b,d] = x0*Wxy[d,0] + x1*Wxy[d,1] + x2*Wseg[d] + b_xy[d] + b_seg[d] + pe[s,d]
// Shapes: x[256,256,3], W_xy[1024,2], b_xy[1024], W_seg[1024,1], b_seg[1024],
//         pe[256,1,1024], out[256,256,1024] fp32.
// Pure HBM-store-bound: 256 MiB writes, ~1.8 MiB reads.

#define D_MODEL 1024
#define SEQ     256
#define BATCH   256
#define BCHUNK  64   // batch elements per block

__global__ __launch_bounds__(256, 1)
void pe_fused_kernel(const float* __restrict__ x,
                     const float* __restrict__ W_xy,
                     const float* __restrict__ b_xy,
                     const float* __restrict__ W_seg,
                     const float* __restrict__ b_seg,
                     const float* __restrict__ pe,
                     float* __restrict__ out)
{
    const int t  = threadIdx.x;        // 0..255, owns d = 4t..4t+3
    const int s  = blockIdx.y;         // 0..255
    const int b0 = blockIdx.x * BCHUNK;
    const int d  = t << 2;

    // --- per-d constants, loaded once per block into registers ---
    // W_xy is [D,2] interleaved: deswizzle two float4s into wx / wy lanes.
    const float4 w0 = *reinterpret_cast<const float4*>(W_xy + 2 * d);
    const float4 w1 = *reinterpret_cast<const float4*>(W_xy + 2 * d + 4);
    const float4 wx = make_float4(w0.x, w0.z, w1.x, w1.z);
    const float4 wy = make_float4(w0.y, w0.w, w1.y, w1.w);
    const float4 ws = *reinterpret_cast<const float4*>(W_seg + d);

    const float4 bx = *reinterpret_cast<const float4*>(b_xy + d);
    const float4 bs = *reinterpret_cast<const float4*>(b_seg + d);
    const float4 p  = *reinterpret_cast<const float4*>(pe + (size_t)s * D_MODEL + d);

    const float4 c = make_float4(p.x + bx.x + bs.x,
                                 p.y + bx.y + bs.y,
                                 p.z + bx.z + bs.z,
                                 p.w + bx.w + bs.w);

    const float* xp = x + ((size_t)(s * BATCH + b0)) * 3;
    float*       op = out + ((size_t)(s * BATCH + b0)) * D_MODEL + d;

    #pragma unroll 4
    for (int i = 0; i < BCHUNK; ++i) {
        // 3 scalar loads, uniform across the warp (broadcast, L1-resident)
        const float x0 = __ldg(xp + i * 3 + 0);
        const float x1 = __ldg(xp + i * 3 + 1);
        const float x2 = __ldg(xp + i * 3 + 2);

        float4 o;
        o.x = fmaf(x0, wx.x, fmaf(x1, wy.x, fmaf(x2, ws.x, c.x)));
        o.y = fmaf(x0, wx.y, fmaf(x1, wy.y, fmaf(x2, ws.y, c.y)));
        o.z = fmaf(x0, wx.z, fmaf(x1, wy.z, fmaf(x2, ws.z, c.z)));
        o.w = fmaf(x0, wx.w, fmaf(x1, wy.w, fmaf(x2, ws.w, c.w)));

        *reinterpret_cast<float4*>(op + (size_t)i * D_MODEL) = o;
    }
}

extern "C" void kernel_launch(void* const* d_in, const int* in_sizes, int n_in,
                              void* d_out, int out_size)
{
    const float* x     = (const float*)d_in[0];
    const float* W_xy  = (const float*)d_in[1];
    const float* b_xy  = (const float*)d_in[2];
    const float* W_seg = (const float*)d_in[3];
    const float* b_seg = (const float*)d_in[4];
    const float* pe    = (const float*)d_in[5];
    float* out = (float*)d_out;

    dim3 grid(BATCH / BCHUNK, SEQ);   // (4, 256) = 1024 blocks
    dim3 block(256);
    pe_fused_kernel<<<grid, block>>>(x, W_xy, b_xy, W_seg, b_seg, pe, out);
}

// round 2
// speedup vs baseline: 1.1787x; 1.1787x over previous
#include <cuda_runtime.h>

// out[s,b,d] = x0*Wxy[d,0] + x1*Wxy[d,1] + x2*Wseg[d] + b_xy[d] + b_seg[d] + pe[s,d]
// Shapes: x[256,256,3], W_xy[1024,2], b_xy[1024], W_seg[1024,1], b_seg[1024],
//         pe[256,1,1024], out[256,256,1024] fp32.
// Pure HBM-store-bound: 256 MiB writes, ~1.8 MiB reads.
//
// R2 changes vs R1 (49.2us, DRAM 58.8%, occ 50.4%):
//  - BCHUNK 64 -> 16 (4096 blocks: per-SM balance ~3% instead of ~14%)
//  - __launch_bounds__(256, 6): occupancy 4 -> 6 CTAs/SM (more outstanding stores)
//  - __stcs streaming stores (write-once data, evict-first in L2)

#define D_MODEL 1024
#define SEQ     256
#define BATCH   256
#define BCHUNK  16   // batch elements per block

__global__ __launch_bounds__(256, 6)
void pe_fused_kernel(const float* __restrict__ x,
                     const float* __restrict__ W_xy,
                     const float* __restrict__ b_xy,
                     const float* __restrict__ W_seg,
                     const float* __restrict__ b_seg,
                     const float* __restrict__ pe,
                     float* __restrict__ out)
{
    const int t  = threadIdx.x;        // 0..255, owns d = 4t..4t+3
    const int s  = blockIdx.y;         // 0..255
    const int b0 = blockIdx.x * BCHUNK;
    const int d  = t << 2;

    // --- per-d constants, loaded once per block into registers ---
    // W_xy is [D,2] interleaved: deswizzle two float4s into wx / wy lanes.
    const float4 w0 = *reinterpret_cast<const float4*>(W_xy + 2 * d);
    const float4 w1 = *reinterpret_cast<const float4*>(W_xy + 2 * d + 4);
    const float4 wx = make_float4(w0.x, w0.z, w1.x, w1.z);
    const float4 wy = make_float4(w0.y, w0.w, w1.y, w1.w);
    const float4 ws = *reinterpret_cast<const float4*>(W_seg + d);

    const float4 bx = *reinterpret_cast<const float4*>(b_xy + d);
    const float4 bs = *reinterpret_cast<const float4*>(b_seg + d);
    const float4 p  = *reinterpret_cast<const float4*>(pe + (size_t)s * D_MODEL + d);

    const float4 c = make_float4(p.x + bx.x + bs.x,
                                 p.y + bx.y + bs.y,
                                 p.z + bx.z + bs.z,
                                 p.w + bx.w + bs.w);

    const float* xp = x + ((size_t)(s * BATCH + b0)) * 3;
    float*       op = out + ((size_t)(s * BATCH + b0)) * D_MODEL + d;

    #pragma unroll
    for (int i = 0; i < BCHUNK; ++i) {
        // 3 scalar loads, uniform across the warp (broadcast, L1/L2-resident)
        const float x0 = __ldg(xp + i * 3 + 0);
        const float x1 = __ldg(xp + i * 3 + 1);
        const float x2 = __ldg(xp + i * 3 + 2);

        float4 o;
        o.x = fmaf(x0, wx.x, fmaf(x1, wy.x, fmaf(x2, ws.x, c.x)));
        o.y = fmaf(x0, wx.y, fmaf(x1, wy.y, fmaf(x2, ws.y, c.y)));
        o.z = fmaf(x0, wx.z, fmaf(x1, wy.z, fmaf(x2, ws.z, c.z)));
        o.w = fmaf(x0, wx.w, fmaf(x1, wy.w, fmaf(x2, ws.w, c.w)));

        // streaming store: write-once, never re-read -> evict-first
        __stcs(reinterpret_cast<float4*>(op + (size_t)i * D_MODEL), o);
    }
}

extern "C" void kernel_launch(void* const* d_in, const int* in_sizes, int n_in,
                              void* d_out, int out_size)
{
    const float* x     = (const float*)d_in[0];
    const float* W_xy  = (const float*)d_in[1];
    const float* b_xy  = (const float*)d_in[2];
    const float* W_seg = (const float*)d_in[3];
    const float* b_seg = (const float*)d_in[4];
    const float* pe    = (const float*)d_in[5];
    float* out = (float*)d_out;

    dim3 grid(BATCH / BCHUNK, SEQ);   // (16, 256) = 4096 blocks
    dim3 block(256);
    pe_fused_kernel<<<grid, block>>>(x, W_xy, b_xy, W_seg, b_seg, pe, out);
}